// round 1
// baseline (speedup 1.0000x reference)
#include <cuda_runtime.h>
#include <cuda_bf16.h>
#include <math.h>

// ---------------------------------------------------------------------------
// BasicMambaBlock: fp32 baseline
//   ln1 -> gemm(w_in) -> conv+silu -> gemm(w_x) -> gemm(w_dt)+softplus ->
//   selective scan (fused skip + silu(z)) -> gemm(w_out)+residual ->
//   ln2 -> gemm(w_ff1)+bias -> geglu -> gemm(w_ff2)+bias+residual
// ---------------------------------------------------------------------------

#define TOKENS   4096      // B*L
#define DMODEL   1024
#define DINNER   2048
#define DSTATE   16
#define DTRANK   64
#define FFIN     4096
#define LSEQ     2048

// scratch (static device globals: allocation-free rule)
__device__ float g_h    [TOKENS * DMODEL];      // ln1 output
__device__ float g_xz   [TOKENS * 2 * DINNER];  // [xc_raw | z]
__device__ float g_xc   [TOKENS * DINNER];      // conv+silu output
__device__ float g_dbc  [TOKENS * 96];          // [dt_lo(64) | B(16) | C(16)]
__device__ float g_dt   [TOKENS * DINNER];      // softplus dt
__device__ float g_y    [TOKENS * DINNER];      // scan output (fully fused)
__device__ float g_out1 [TOKENS * DMODEL];      // x + mamba
__device__ float g_h2   [TOKENS * DMODEL];      // ln2 output
__device__ float g_p    [TOKENS * 2 * FFIN];    // ff1 output
__device__ float g_ffa  [TOKENS * FFIN];        // a * gelu(g)

__device__ __forceinline__ float softplus_f(float x) {
    return (x > 20.f) ? x : log1pf(expf(x));
}

// ---------------------------------------------------------------------------
// LayerNorm: one block per token, D=1024, 256 threads (float4 per thread)
// ---------------------------------------------------------------------------
__global__ void __launch_bounds__(256) ln_kernel(
    const float* __restrict__ x, const float* __restrict__ g,
    const float* __restrict__ b, float* __restrict__ out)
{
    int t = blockIdx.x, tid = threadIdx.x;
    float4 v = ((const float4*)(x + (size_t)t * DMODEL))[tid];
    float s  = v.x + v.y + v.z + v.w;
    float ss = fmaf(v.x, v.x, fmaf(v.y, v.y, fmaf(v.z, v.z, v.w * v.w)));
    #pragma unroll
    for (int o = 16; o > 0; o >>= 1) {
        s  += __shfl_down_sync(0xffffffffu, s, o);
        ss += __shfl_down_sync(0xffffffffu, ss, o);
    }
    __shared__ float rs_[8], rss_[8];
    __shared__ float smu, srs;
    int warp = tid >> 5, lane = tid & 31;
    if (lane == 0) { rs_[warp] = s; rss_[warp] = ss; }
    __syncthreads();
    if (tid == 0) {
        float S = 0.f, SS = 0.f;
        #pragma unroll
        for (int w = 0; w < 8; w++) { S += rs_[w]; SS += rss_[w]; }
        float mu  = S * (1.f / DMODEL);
        float var = SS * (1.f / DMODEL) - mu * mu;
        smu = mu;
        srs = rsqrtf(var + 1e-5f);
    }
    __syncthreads();
    float mu = smu, rs = srs;
    float4 gv = ((const float4*)g)[tid];
    float4 bv = ((const float4*)b)[tid];
    float4 o;
    o.x = (v.x - mu) * rs * gv.x + bv.x;
    o.y = (v.y - mu) * rs * gv.y + bv.y;
    o.z = (v.z - mu) * rs * gv.z + bv.z;
    o.w = (v.w - mu) * rs * gv.w + bv.w;
    ((float4*)(out + (size_t)t * DMODEL))[tid] = o;
}

// ---------------------------------------------------------------------------
// Generic fp32 GEMM: C[M,N] = A[M,K] (lda) @ B[K,N]   (M%128==0, N%128==0, K%8==0)
// MODE bits: 1=+bias[n], 4=softplus (after bias), 2=+res[m,n]
// 128x128 tile, BK=8, 256 threads, 8x8 microtile
// ---------------------------------------------------------------------------
template <int MODE>
__global__ void __launch_bounds__(256) gemm_kernel(
    const float* __restrict__ A, int lda,
    const float* __restrict__ B,
    float* __restrict__ C,
    const float* __restrict__ bias,
    const float* __restrict__ res,
    int M, int N, int K)
{
    __shared__ float As[8][128];
    __shared__ float Bs[8][128];
    int tid = threadIdx.x;
    int m0 = blockIdx.y * 128;
    int n0 = blockIdx.x * 128;

    int ar = tid >> 1;          // 0..127
    int ac = (tid & 1) * 4;     // 0 or 4
    int br = tid >> 5;          // 0..7
    int bc = (tid & 31) * 4;    // 0..124

    int ty = tid >> 4;          // 0..15 -> rows ty*8..+7
    int tx = tid & 15;          // 0..15 -> cols tx*8..+7

    float acc[8][8];
    #pragma unroll
    for (int i = 0; i < 8; i++)
        #pragma unroll
        for (int j = 0; j < 8; j++) acc[i][j] = 0.f;

    for (int k0 = 0; k0 < K; k0 += 8) {
        float4 av = *(const float4*)(A + (size_t)(m0 + ar) * lda + k0 + ac);
        float4 bv = *(const float4*)(B + (size_t)(k0 + br) * N + n0 + bc);
        As[ac + 0][ar] = av.x;
        As[ac + 1][ar] = av.y;
        As[ac + 2][ar] = av.z;
        As[ac + 3][ar] = av.w;
        *(float4*)(&Bs[br][bc]) = bv;
        __syncthreads();
        #pragma unroll
        for (int k = 0; k < 8; k++) {
            float a[8], b8[8];
            *(float4*)(a)      = *(const float4*)(&As[k][ty * 8]);
            *(float4*)(a + 4)  = *(const float4*)(&As[k][ty * 8 + 4]);
            *(float4*)(b8)     = *(const float4*)(&Bs[k][tx * 8]);
            *(float4*)(b8 + 4) = *(const float4*)(&Bs[k][tx * 8 + 4]);
            #pragma unroll
            for (int i = 0; i < 8; i++)
                #pragma unroll
                for (int j = 0; j < 8; j++)
                    acc[i][j] = fmaf(a[i], b8[j], acc[i][j]);
        }
        __syncthreads();
    }

    #pragma unroll
    for (int i = 0; i < 8; i++) {
        int row = m0 + ty * 8 + i;
        #pragma unroll
        for (int j4 = 0; j4 < 8; j4 += 4) {
            int col = n0 + tx * 8 + j4;
            float4 v = make_float4(acc[i][j4], acc[i][j4 + 1], acc[i][j4 + 2], acc[i][j4 + 3]);
            if (MODE & 1) {
                float4 bv = *(const float4*)(bias + col);
                v.x += bv.x; v.y += bv.y; v.z += bv.z; v.w += bv.w;
            }
            if (MODE & 4) {
                v.x = softplus_f(v.x); v.y = softplus_f(v.y);
                v.z = softplus_f(v.z); v.w = softplus_f(v.w);
            }
            if (MODE & 2) {
                float4 rv = *(const float4*)(res + (size_t)row * N + col);
                v.x += rv.x; v.y += rv.y; v.z += rv.z; v.w += rv.w;
            }
            *(float4*)(C + (size_t)row * N + col) = v;
        }
    }
}

// ---------------------------------------------------------------------------
// depthwise causal conv (D_CONV=4) + bias + silu, over [xc | z] buffer
// ---------------------------------------------------------------------------
__global__ void __launch_bounds__(256) conv_silu_kernel(
    const float* __restrict__ xz, const float* __restrict__ w,
    const float* __restrict__ cb, float* __restrict__ out)
{
    int idx = blockIdx.x * 256 + threadIdx.x;     // < TOKENS*DINNER
    int d = idx & (DINNER - 1);
    int t = idx >> 11;
    int l = t & (LSEQ - 1);
    float w0 = w[d * 4 + 0], w1 = w[d * 4 + 1], w2 = w[d * 4 + 2], w3 = w[d * 4 + 3];
    float s = cb[d];
    const float* base = xz + (size_t)t * (2 * DINNER) + d;
    if (l >= 3) s = fmaf(w0, base[-3 * (size_t)(2 * DINNER)], s);
    if (l >= 2) s = fmaf(w1, base[-2 * (size_t)(2 * DINNER)], s);
    if (l >= 1) s = fmaf(w2, base[-1 * (size_t)(2 * DINNER)], s);
    s = fmaf(w3, base[0], s);
    out[idx] = s / (1.f + expf(-s));   // silu
}

// ---------------------------------------------------------------------------
// dbc = xc @ w_x   (M=4096, K=2048, N=96)  — 32x96 tile, BK=64
// ---------------------------------------------------------------------------
__global__ void __launch_bounds__(256) wx_kernel(
    const float* __restrict__ A, const float* __restrict__ W,
    float* __restrict__ C)
{
    __shared__ float As[64][33];
    __shared__ float Ws[64][96];
    int tid = threadIdx.x;
    int m0 = blockIdx.x * 32;
    int ty = tid >> 4;   // 0..15 -> 2 rows each
    int tx = tid & 15;   // 0..15 -> 6 cols each
    float acc[2][6];
    #pragma unroll
    for (int i = 0; i < 2; i++)
        #pragma unroll
        for (int j = 0; j < 6; j++) acc[i][j] = 0.f;

    for (int k0 = 0; k0 < DINNER; k0 += 64) {
        #pragma unroll
        for (int q = 0; q < 2; q++) {
            int f = tid * 2 + q;
            int r = f >> 4;
            int c = (f & 15) * 4;
            float4 v = *(const float4*)(A + (size_t)(m0 + r) * DINNER + k0 + c);
            As[c + 0][r] = v.x; As[c + 1][r] = v.y;
            As[c + 2][r] = v.z; As[c + 3][r] = v.w;
        }
        #pragma unroll
        for (int q = 0; q < 6; q++) {
            int f = tid + 256 * q;
            int r = f / 24;
            int c = (f % 24) * 4;
            *(float4*)(&Ws[r][c]) = *(const float4*)(W + (size_t)(k0 + r) * 96 + c);
        }
        __syncthreads();
        #pragma unroll 8
        for (int k = 0; k < 64; k++) {
            float a0 = As[k][ty * 2], a1 = As[k][ty * 2 + 1];
            #pragma unroll
            for (int j = 0; j < 6; j++) {
                float bb = Ws[k][tx * 6 + j];
                acc[0][j] = fmaf(a0, bb, acc[0][j]);
                acc[1][j] = fmaf(a1, bb, acc[1][j]);
            }
        }
        __syncthreads();
    }
    #pragma unroll
    for (int i = 0; i < 2; i++)
        #pragma unroll
        for (int j = 0; j < 6; j++)
            C[(size_t)(m0 + ty * 2 + i) * 96 + tx * 6 + j] = acc[i][j];
}

// ---------------------------------------------------------------------------
// selective scan: warp = 2 channels x 16 state lanes; sequential over L,
// fused epilogue (+d_skip*xc, *silu(z)); distance-1 prefetch
// ---------------------------------------------------------------------------
__global__ void __launch_bounds__(256) scan_kernel(
    const float* __restrict__ dt, const float* __restrict__ xc,
    const float* __restrict__ dbc, const float* __restrict__ xz,
    const float* __restrict__ a_log, const float* __restrict__ d_skip,
    float* __restrict__ y)
{
    int warp = threadIdx.x >> 5;
    int lane = threadIdx.x & 31;
    int half = lane >> 4;
    int n    = lane & 15;
    int gchan = blockIdx.x * 16 + warp * 2 + half;  // 0..4095 = b*2048 + d
    int b = gchan >> 11;
    int d = gchan & (DINNER - 1);
    float Acoef = -expf(a_log[d * DSTATE + n]);
    float Dsk   = d_skip[d];

    float s = 0.f;
    int t0 = b * LSEQ;
    // prefetch l=0
    float dt_c = dt [(size_t)t0 * DINNER + d];
    float x_c  = xc [(size_t)t0 * DINNER + d];
    float B_c  = dbc[(size_t)t0 * 96 + 64 + n];
    float C_c  = dbc[(size_t)t0 * 96 + 80 + n];
    float z_c  = (n == 0) ? xz[(size_t)t0 * (2 * DINNER) + DINNER + d] : 0.f;

    for (int l = 0; l < LSEQ; l++) {
        int t = t0 + l;
        float dt_n = 0.f, x_n = 0.f, B_n = 0.f, C_n = 0.f, z_n = 0.f;
        if (l + 1 < LSEQ) {
            int t2 = t + 1;
            dt_n = dt [(size_t)t2 * DINNER + d];
            x_n  = xc [(size_t)t2 * DINNER + d];
            B_n  = dbc[(size_t)t2 * 96 + 64 + n];
            C_n  = dbc[(size_t)t2 * 96 + 80 + n];
            if (n == 0) z_n = xz[(size_t)t2 * (2 * DINNER) + DINNER + d];
        }
        float dA = __expf(dt_c * Acoef);
        s = fmaf(s, dA, dt_c * x_c * B_c);
        float part = s * C_c;
        part += __shfl_down_sync(0xffffffffu, part, 8, 16);
        part += __shfl_down_sync(0xffffffffu, part, 4, 16);
        part += __shfl_down_sync(0xffffffffu, part, 2, 16);
        part += __shfl_down_sync(0xffffffffu, part, 1, 16);
        if (n == 0) {
            float yv = part + Dsk * x_c;
            yv = yv * (z_c / (1.f + __expf(-z_c)));   // * silu(z)
            y[(size_t)t * DINNER + d] = yv;
        }
        dt_c = dt_n; x_c = x_n; B_c = B_n; C_c = C_n; z_c = z_n;
    }
}

// ---------------------------------------------------------------------------
// geglu activation: ffa[t,j] = p[t,j] * gelu_tanh(p[t,4096+j])
// ---------------------------------------------------------------------------
__global__ void __launch_bounds__(256) geglu_kernel(
    const float* __restrict__ p, float* __restrict__ out)
{
    int idx = blockIdx.x * 256 + threadIdx.x;   // < TOKENS*FFIN
    int t = idx >> 12;
    int j = idx & (FFIN - 1);
    float a = p[(size_t)t * (2 * FFIN) + j];
    float g = p[(size_t)t * (2 * FFIN) + FFIN + j];
    float inner = 0.7978845608028654f * fmaf(0.044715f * g * g, g, g);
    float ge = 0.5f * g * (1.f + tanhf(inner));
    out[idx] = a * ge;
}

// ---------------------------------------------------------------------------
extern "C" void kernel_launch(void* const* d_in, const int* in_sizes, int n_in,
                              void* d_out, int out_size)
{
    const float* x      = (const float*)d_in[0];
    const float* ln1_g  = (const float*)d_in[1];
    const float* ln1_b  = (const float*)d_in[2];
    const float* w_in   = (const float*)d_in[3];
    const float* conv_w = (const float*)d_in[4];
    const float* conv_b = (const float*)d_in[5];
    const float* w_x    = (const float*)d_in[6];
    const float* w_dt   = (const float*)d_in[7];
    const float* b_dt   = (const float*)d_in[8];
    const float* a_log  = (const float*)d_in[9];
    const float* d_skip = (const float*)d_in[10];
    const float* w_out  = (const float*)d_in[11];
    const float* ln2_g  = (const float*)d_in[12];
    const float* ln2_b  = (const float*)d_in[13];
    const float* w_ff1  = (const float*)d_in[14];
    const float* b_ff1  = (const float*)d_in[15];
    const float* w_ff2  = (const float*)d_in[16];
    const float* b_ff2  = (const float*)d_in[17];
    float* out = (float*)d_out;

    float *h, *xz, *xc, *dbc, *dtb, *y, *out1, *h2, *p, *ffa;
    cudaGetSymbolAddress((void**)&h,    g_h);
    cudaGetSymbolAddress((void**)&xz,   g_xz);
    cudaGetSymbolAddress((void**)&xc,   g_xc);
    cudaGetSymbolAddress((void**)&dbc,  g_dbc);
    cudaGetSymbolAddress((void**)&dtb,  g_dt);
    cudaGetSymbolAddress((void**)&y,    g_y);
    cudaGetSymbolAddress((void**)&out1, g_out1);
    cudaGetSymbolAddress((void**)&h2,   g_h2);
    cudaGetSymbolAddress((void**)&p,    g_p);
    cudaGetSymbolAddress((void**)&ffa,  g_ffa);

    // 1. ln1
    ln_kernel<<<TOKENS, 256>>>(x, ln1_g, ln1_b, h);
    // 2. xz = h @ w_in          [4096,1024]@[1024,4096]
    gemm_kernel<0><<<dim3(4096 / 128, TOKENS / 128), 256>>>(
        h, DMODEL, w_in, xz, nullptr, nullptr, TOKENS, 4096, DMODEL);
    // 3. conv + silu
    conv_silu_kernel<<<(TOKENS * DINNER) / 256, 256>>>(xz, conv_w, conv_b, xc);
    // 4. dbc = xc @ w_x         [4096,2048]@[2048,96]
    wx_kernel<<<TOKENS / 32, 256>>>(xc, w_x, dbc);
    // 5. dt = softplus(dt_lo @ w_dt + b_dt)   [4096,64(lda 96)]@[64,2048]
    gemm_kernel<5><<<dim3(DINNER / 128, TOKENS / 128), 256>>>(
        dbc, 96, w_dt, dtb, b_dt, nullptr, TOKENS, DINNER, DTRANK);
    // 6. selective scan (fused skip + silu(z))
    scan_kernel<<<(2 * DINNER) / 16, 256>>>(dtb, xc, dbc, xz, a_log, d_skip, y);
    // 7. out1 = x + y @ w_out   [4096,2048]@[2048,1024]
    gemm_kernel<2><<<dim3(DMODEL / 128, TOKENS / 128), 256>>>(
        y, DINNER, w_out, out1, nullptr, x, TOKENS, DMODEL, DINNER);
    // 8. ln2
    ln_kernel<<<TOKENS, 256>>>(out1, ln2_g, ln2_b, h2);
    // 9. p = h2 @ w_ff1 + b_ff1   [4096,1024]@[1024,8192]
    gemm_kernel<1><<<dim3((2 * FFIN) / 128, TOKENS / 128), 256>>>(
        h2, DMODEL, w_ff1, p, b_ff1, nullptr, TOKENS, 2 * FFIN, DMODEL);
    // 10. geglu
    geglu_kernel<<<(TOKENS * FFIN) / 256, 256>>>(p, ffa);
    // 11. out = out1 + ffa @ w_ff2 + b_ff2   [4096,4096]@[4096,1024]
    gemm_kernel<3><<<dim3(DMODEL / 128, TOKENS / 128), 256>>>(
        ffa, FFIN, w_ff2, out, b_ff2, out1, TOKENS, DMODEL, FFIN);
}

// round 2
// speedup vs baseline: 1.0051x; 1.0051x over previous
#include <cuda_runtime.h>
#include <cuda_bf16.h>
#include <math.h>

// ---------------------------------------------------------------------------
// BasicMambaBlock: fp32 baseline
//   ln1 -> gemm(w_in) -> conv+silu -> gemm(w_x) -> gemm(w_dt)+softplus ->
//   selective scan (fused skip + silu(z)) -> gemm(w_out)+residual ->
//   ln2 -> gemm(w_ff1)+bias -> geglu -> gemm(w_ff2)+bias+residual
// ---------------------------------------------------------------------------

#define TOKENS   4096      // B*L
#define DMODEL   1024
#define DINNER   2048
#define DSTATE   16
#define DTRANK   64
#define FFIN     4096
#define LSEQ     2048

// scratch (static device globals: allocation-free rule)
__device__ float g_h    [TOKENS * DMODEL];      // ln1 output
__device__ float g_xz   [TOKENS * 2 * DINNER];  // [xc_raw | z]
__device__ float g_xc   [TOKENS * DINNER];      // conv+silu output
__device__ float g_dbc  [TOKENS * 96];          // [dt_lo(64) | B(16) | C(16)]
__device__ float g_dt   [TOKENS * DINNER];      // softplus dt
__device__ float g_y    [TOKENS * DINNER];      // scan output (fully fused)
__device__ float g_out1 [TOKENS * DMODEL];      // x + mamba
__device__ float g_h2   [TOKENS * DMODEL];      // ln2 output
__device__ float g_p    [TOKENS * 2 * FFIN];    // ff1 output
__device__ float g_ffa  [TOKENS * FFIN];        // a * gelu(g)

__device__ __forceinline__ float softplus_f(float x) {
    return (x > 20.f) ? x : log1pf(expf(x));
}

// ---------------------------------------------------------------------------
// LayerNorm: one block per token, D=1024, 256 threads (float4 per thread)
// ---------------------------------------------------------------------------
__global__ void __launch_bounds__(256) ln_kernel(
    const float* __restrict__ x, const float* __restrict__ g,
    const float* __restrict__ b, float* __restrict__ out)
{
    int t = blockIdx.x, tid = threadIdx.x;
    float4 v = ((const float4*)(x + (size_t)t * DMODEL))[tid];
    float s  = v.x + v.y + v.z + v.w;
    float ss = fmaf(v.x, v.x, fmaf(v.y, v.y, fmaf(v.z, v.z, v.w * v.w)));
    #pragma unroll
    for (int o = 16; o > 0; o >>= 1) {
        s  += __shfl_down_sync(0xffffffffu, s, o);
        ss += __shfl_down_sync(0xffffffffu, ss, o);
    }
    __shared__ float rs_[8], rss_[8];
    __shared__ float smu, srs;
    int warp = tid >> 5, lane = tid & 31;
    if (lane == 0) { rs_[warp] = s; rss_[warp] = ss; }
    __syncthreads();
    if (tid == 0) {
        float S = 0.f, SS = 0.f;
        #pragma unroll
        for (int w = 0; w < 8; w++) { S += rs_[w]; SS += rss_[w]; }
        float mu  = S * (1.f / DMODEL);
        float var = SS * (1.f / DMODEL) - mu * mu;
        smu = mu;
        srs = rsqrtf(var + 1e-5f);
    }
    __syncthreads();
    float mu = smu, rs = srs;
    float4 gv = ((const float4*)g)[tid];
    float4 bv = ((const float4*)b)[tid];
    float4 o;
    o.x = (v.x - mu) * rs * gv.x + bv.x;
    o.y = (v.y - mu) * rs * gv.y + bv.y;
    o.z = (v.z - mu) * rs * gv.z + bv.z;
    o.w = (v.w - mu) * rs * gv.w + bv.w;
    ((float4*)(out + (size_t)t * DMODEL))[tid] = o;
}

// ---------------------------------------------------------------------------
// Generic fp32 GEMM: C[M,N] = A[M,K] (lda) @ B[K,N]   (M%128==0, N%128==0, K%8==0)
// MODE bits: 1=+bias[n], 4=softplus (after bias), 2=+res[m,n]
// 128x128 tile, BK=8, 256 threads, 8x8 microtile
// ---------------------------------------------------------------------------
template <int MODE>
__global__ void __launch_bounds__(256) gemm_kernel(
    const float* __restrict__ A, int lda,
    const float* __restrict__ B,
    float* __restrict__ C,
    const float* __restrict__ bias,
    const float* __restrict__ res,
    int M, int N, int K)
{
    __shared__ float As[8][128];
    __shared__ float Bs[8][128];
    int tid = threadIdx.x;
    int m0 = blockIdx.y * 128;
    int n0 = blockIdx.x * 128;

    int ar = tid >> 1;          // 0..127
    int ac = (tid & 1) * 4;     // 0 or 4
    int br = tid >> 5;          // 0..7
    int bc = (tid & 31) * 4;    // 0..124

    int ty = tid >> 4;          // 0..15 -> rows ty*8..+7
    int tx = tid & 15;          // 0..15 -> cols tx*8..+7

    float acc[8][8];
    #pragma unroll
    for (int i = 0; i < 8; i++)
        #pragma unroll
        for (int j = 0; j < 8; j++) acc[i][j] = 0.f;

    for (int k0 = 0; k0 < K; k0 += 8) {
        float4 av = *(const float4*)(A + (size_t)(m0 + ar) * lda + k0 + ac);
        float4 bv = *(const float4*)(B + (size_t)(k0 + br) * N + n0 + bc);
        As[ac + 0][ar] = av.x;
        As[ac + 1][ar] = av.y;
        As[ac + 2][ar] = av.z;
        As[ac + 3][ar] = av.w;
        *(float4*)(&Bs[br][bc]) = bv;
        __syncthreads();
        #pragma unroll
        for (int k = 0; k < 8; k++) {
            float a[8], b8[8];
            *(float4*)(a)      = *(const float4*)(&As[k][ty * 8]);
            *(float4*)(a + 4)  = *(const float4*)(&As[k][ty * 8 + 4]);
            *(float4*)(b8)     = *(const float4*)(&Bs[k][tx * 8]);
            *(float4*)(b8 + 4) = *(const float4*)(&Bs[k][tx * 8 + 4]);
            #pragma unroll
            for (int i = 0; i < 8; i++)
                #pragma unroll
                for (int j = 0; j < 8; j++)
                    acc[i][j] = fmaf(a[i], b8[j], acc[i][j]);
        }
        __syncthreads();
    }

    #pragma unroll
    for (int i = 0; i < 8; i++) {
        int row = m0 + ty * 8 + i;
        #pragma unroll
        for (int j4 = 0; j4 < 8; j4 += 4) {
            int col = n0 + tx * 8 + j4;
            float4 v = make_float4(acc[i][j4], acc[i][j4 + 1], acc[i][j4 + 2], acc[i][j4 + 3]);
            if (MODE & 1) {
                float4 bv = *(const float4*)(bias + col);
                v.x += bv.x; v.y += bv.y; v.z += bv.z; v.w += bv.w;
            }
            if (MODE & 4) {
                v.x = softplus_f(v.x); v.y = softplus_f(v.y);
                v.z = softplus_f(v.z); v.w = softplus_f(v.w);
            }
            if (MODE & 2) {
                float4 rv = *(const float4*)(res + (size_t)row * N + col);
                v.x += rv.x; v.y += rv.y; v.z += rv.z; v.w += rv.w;
            }
            *(float4*)(C + (size_t)row * N + col) = v;
        }
    }
}

// ---------------------------------------------------------------------------
// depthwise causal conv (D_CONV=4) + bias + silu, over [xc | z] buffer
// ---------------------------------------------------------------------------
__global__ void __launch_bounds__(256) conv_silu_kernel(
    const float* __restrict__ xz, const float* __restrict__ w,
    const float* __restrict__ cb, float* __restrict__ out)
{
    int idx = blockIdx.x * 256 + threadIdx.x;     // < TOKENS*DINNER
    int d = idx & (DINNER - 1);
    int t = idx >> 11;
    int l = t & (LSEQ - 1);
    float w0 = w[d * 4 + 0], w1 = w[d * 4 + 1], w2 = w[d * 4 + 2], w3 = w[d * 4 + 3];
    float s = cb[d];
    const float* base = xz + (size_t)t * (2 * DINNER) + d;
    if (l >= 3) s = fmaf(w0, base[-3 * (size_t)(2 * DINNER)], s);
    if (l >= 2) s = fmaf(w1, base[-2 * (size_t)(2 * DINNER)], s);
    if (l >= 1) s = fmaf(w2, base[-1 * (size_t)(2 * DINNER)], s);
    s = fmaf(w3, base[0], s);
    out[idx] = s / (1.f + expf(-s));   // silu
}

// ---------------------------------------------------------------------------
// dbc = xc @ w_x   (M=4096, K=2048, N=96)  — 32x96 tile, BK=64
// ---------------------------------------------------------------------------
__global__ void __launch_bounds__(256) wx_kernel(
    const float* __restrict__ A, const float* __restrict__ W,
    float* __restrict__ C)
{
    __shared__ float As[64][33];
    __shared__ float Ws[64][96];
    int tid = threadIdx.x;
    int m0 = blockIdx.x * 32;
    int ty = tid >> 4;   // 0..15 -> 2 rows each
    int tx = tid & 15;   // 0..15 -> 6 cols each
    float acc[2][6];
    #pragma unroll
    for (int i = 0; i < 2; i++)
        #pragma unroll
        for (int j = 0; j < 6; j++) acc[i][j] = 0.f;

    for (int k0 = 0; k0 < DINNER; k0 += 64) {
        #pragma unroll
        for (int q = 0; q < 2; q++) {
            int f = tid * 2 + q;
            int r = f >> 4;
            int c = (f & 15) * 4;
            float4 v = *(const float4*)(A + (size_t)(m0 + r) * DINNER + k0 + c);
            As[c + 0][r] = v.x; As[c + 1][r] = v.y;
            As[c + 2][r] = v.z; As[c + 3][r] = v.w;
        }
        #pragma unroll
        for (int q = 0; q < 6; q++) {
            int f = tid + 256 * q;
            int r = f / 24;
            int c = (f % 24) * 4;
            *(float4*)(&Ws[r][c]) = *(const float4*)(W + (size_t)(k0 + r) * 96 + c);
        }
        __syncthreads();
        #pragma unroll 8
        for (int k = 0; k < 64; k++) {
            float a0 = As[k][ty * 2], a1 = As[k][ty * 2 + 1];
            #pragma unroll
            for (int j = 0; j < 6; j++) {
                float bb = Ws[k][tx * 6 + j];
                acc[0][j] = fmaf(a0, bb, acc[0][j]);
                acc[1][j] = fmaf(a1, bb, acc[1][j]);
            }
        }
        __syncthreads();
    }
    #pragma unroll
    for (int i = 0; i < 2; i++)
        #pragma unroll
        for (int j = 0; j < 6; j++)
            C[(size_t)(m0 + ty * 2 + i) * 96 + tx * 6 + j] = acc[i][j];
}

// ---------------------------------------------------------------------------
// selective scan: warp = 2 channels x 16 state lanes; sequential over L,
// fused epilogue (+d_skip*xc, *silu(z)); distance-1 prefetch
// ---------------------------------------------------------------------------
__global__ void __launch_bounds__(256) scan_kernel(
    const float* __restrict__ dt, const float* __restrict__ xc,
    const float* __restrict__ dbc, const float* __restrict__ xz,
    const float* __restrict__ a_log, const float* __restrict__ d_skip,
    float* __restrict__ y)
{
    int warp = threadIdx.x >> 5;
    int lane = threadIdx.x & 31;
    int half = lane >> 4;
    int n    = lane & 15;
    int gchan = blockIdx.x * 16 + warp * 2 + half;  // 0..4095 = b*2048 + d
    int b = gchan >> 11;
    int d = gchan & (DINNER - 1);
    float Acoef = -expf(a_log[d * DSTATE + n]);
    float Dsk   = d_skip[d];

    float s = 0.f;
    int t0 = b * LSEQ;
    // prefetch l=0
    float dt_c = dt [(size_t)t0 * DINNER + d];
    float x_c  = xc [(size_t)t0 * DINNER + d];
    float B_c  = dbc[(size_t)t0 * 96 + 64 + n];
    float C_c  = dbc[(size_t)t0 * 96 + 80 + n];
    float z_c  = (n == 0) ? xz[(size_t)t0 * (2 * DINNER) + DINNER + d] : 0.f;

    for (int l = 0; l < LSEQ; l++) {
        int t = t0 + l;
        float dt_n = 0.f, x_n = 0.f, B_n = 0.f, C_n = 0.f, z_n = 0.f;
        if (l + 1 < LSEQ) {
            int t2 = t + 1;
            dt_n = dt [(size_t)t2 * DINNER + d];
            x_n  = xc [(size_t)t2 * DINNER + d];
            B_n  = dbc[(size_t)t2 * 96 + 64 + n];
            C_n  = dbc[(size_t)t2 * 96 + 80 + n];
            if (n == 0) z_n = xz[(size_t)t2 * (2 * DINNER) + DINNER + d];
        }
        float dA = __expf(dt_c * Acoef);
        s = fmaf(s, dA, dt_c * x_c * B_c);
        float part = s * C_c;
        part += __shfl_down_sync(0xffffffffu, part, 8, 16);
        part += __shfl_down_sync(0xffffffffu, part, 4, 16);
        part += __shfl_down_sync(0xffffffffu, part, 2, 16);
        part += __shfl_down_sync(0xffffffffu, part, 1, 16);
        if (n == 0) {
            float yv = part + Dsk * x_c;
            yv = yv * (z_c / (1.f + __expf(-z_c)));   // * silu(z)
            y[(size_t)t * DINNER + d] = yv;
        }
        dt_c = dt_n; x_c = x_n; B_c = B_n; C_c = C_n; z_c = z_n;
    }
}

// ---------------------------------------------------------------------------
// geglu activation: ffa[t,j] = p[t,j] * gelu_tanh(p[t,4096+j])
// ---------------------------------------------------------------------------
__global__ void __launch_bounds__(256) geglu_kernel(
    const float* __restrict__ p, float* __restrict__ out)
{
    int idx = blockIdx.x * 256 + threadIdx.x;   // < TOKENS*FFIN
    int t = idx >> 12;
    int j = idx & (FFIN - 1);
    float a = p[(size_t)t * (2 * FFIN) + j];
    float g = p[(size_t)t * (2 * FFIN) + FFIN + j];
    float inner = 0.7978845608028654f * fmaf(0.044715f * g * g, g, g);
    float ge = 0.5f * g * (1.f + tanhf(inner));
    out[idx] = a * ge;
}

// ---------------------------------------------------------------------------
extern "C" void kernel_launch(void* const* d_in, const int* in_sizes, int n_in,
                              void* d_out, int out_size)
{
    const float* x      = (const float*)d_in[0];
    const float* ln1_g  = (const float*)d_in[1];
    const float* ln1_b  = (const float*)d_in[2];
    const float* w_in   = (const float*)d_in[3];
    const float* conv_w = (const float*)d_in[4];
    const float* conv_b = (const float*)d_in[5];
    const float* w_x    = (const float*)d_in[6];
    const float* w_dt   = (const float*)d_in[7];
    const float* b_dt   = (const float*)d_in[8];
    const float* a_log  = (const float*)d_in[9];
    const float* d_skip = (const float*)d_in[10];
    const float* w_out  = (const float*)d_in[11];
    const float* ln2_g  = (const float*)d_in[12];
    const float* ln2_b  = (const float*)d_in[13];
    const float* w_ff1  = (const float*)d_in[14];
    const float* b_ff1  = (const float*)d_in[15];
    const float* w_ff2  = (const float*)d_in[16];
    const float* b_ff2  = (const float*)d_in[17];
    float* out = (float*)d_out;

    float *h, *xz, *xc, *dbc, *dtb, *y, *out1, *h2, *p, *ffa;
    cudaGetSymbolAddress((void**)&h,    g_h);
    cudaGetSymbolAddress((void**)&xz,   g_xz);
    cudaGetSymbolAddress((void**)&xc,   g_xc);
    cudaGetSymbolAddress((void**)&dbc,  g_dbc);
    cudaGetSymbolAddress((void**)&dtb,  g_dt);
    cudaGetSymbolAddress((void**)&y,    g_y);
    cudaGetSymbolAddress((void**)&out1, g_out1);
    cudaGetSymbolAddress((void**)&h2,   g_h2);
    cudaGetSymbolAddress((void**)&p,    g_p);
    cudaGetSymbolAddress((void**)&ffa,  g_ffa);

    // 1. ln1
    ln_kernel<<<TOKENS, 256>>>(x, ln1_g, ln1_b, h);
    // 2. xz = h @ w_in          [4096,1024]@[1024,4096]
    gemm_kernel<0><<<dim3(4096 / 128, TOKENS / 128), 256>>>(
        h, DMODEL, w_in, xz, nullptr, nullptr, TOKENS, 4096, DMODEL);
    // 3. conv + silu
    conv_silu_kernel<<<(TOKENS * DINNER) / 256, 256>>>(xz, conv_w, conv_b, xc);
    // 4. dbc = xc @ w_x         [4096,2048]@[2048,96]
    wx_kernel<<<TOKENS / 32, 256>>>(xc, w_x, dbc);
    // 5. dt = softplus(dt_lo @ w_dt + b_dt)   [4096,64(lda 96)]@[64,2048]
    gemm_kernel<5><<<dim3(DINNER / 128, TOKENS / 128), 256>>>(
        dbc, 96, w_dt, dtb, b_dt, nullptr, TOKENS, DINNER, DTRANK);
    // 6. selective scan (fused skip + silu(z))
    scan_kernel<<<(2 * DINNER) / 16, 256>>>(dtb, xc, dbc, xz, a_log, d_skip, y);
    // 7. out1 = x + y @ w_out   [4096,2048]@[2048,1024]
    gemm_kernel<2><<<dim3(DMODEL / 128, TOKENS / 128), 256>>>(
        y, DINNER, w_out, out1, nullptr, x, TOKENS, DMODEL, DINNER);
    // 8. ln2
    ln_kernel<<<TOKENS, 256>>>(out1, ln2_g, ln2_b, h2);
    // 9. p = h2 @ w_ff1 + b_ff1   [4096,1024]@[1024,8192]
    gemm_kernel<1><<<dim3((2 * FFIN) / 128, TOKENS / 128), 256>>>(
        h2, DMODEL, w_ff1, p, b_ff1, nullptr, TOKENS, 2 * FFIN, DMODEL);
    // 10. geglu
    geglu_kernel<<<(TOKENS * FFIN) / 256, 256>>>(p, ffa);
    // 11. out = out1 + ffa @ w_ff2 + b_ff2   [4096,4096]@[4096,1024]
    gemm_kernel<3><<<dim3(DMODEL / 128, TOKENS / 128), 256>>>(
        ffa, FFIN, w_ff2, out, b_ff2, out1, TOKENS, DMODEL, FFIN);
}

// round 4
// speedup vs baseline: 2.1604x; 2.1494x over previous
#include <cuda_runtime.h>
#include <math.h>
#include <stdint.h>

#define TOKENS   4096
#define DMODEL   1024
#define DINNER   2048
#define DSTATE   16
#define DTRANK   64
#define FFIN     4096
#define LSEQ     2048

// ---------------- scratch ----------------
__device__ __align__(128) float g_h    [TOKENS * DMODEL];
__device__ __align__(128) float g_xz   [TOKENS * 2 * DINNER];
__device__ __align__(128) float g_xc   [TOKENS * DINNER];
__device__ __align__(128) float g_dbc  [TOKENS * 96];
__device__ __align__(128) float g_dt   [TOKENS * DINNER];
__device__ __align__(128) float g_y    [TOKENS * DINNER];
__device__ __align__(128) float g_out1 [TOKENS * DMODEL];
__device__ __align__(128) float g_h2   [TOKENS * DMODEL];
__device__ __align__(128) float g_p    [TOKENS * 2 * FFIN];
__device__ __align__(128) float g_ffa  [TOKENS * FFIN];
__device__ __align__(128) float g_wtin [4096 * 1024];
__device__ __align__(128) float g_wtout[1024 * 2048];
__device__ __align__(128) float g_wtff1[8192 * 1024];
__device__ __align__(128) float g_wtff2[1024 * 4096];

// ---------------- helpers ----------------
__device__ __forceinline__ float to_tf32(float x) {
    uint32_t r;
    asm("cvt.rna.tf32.f32 %0, %1;" : "=r"(r) : "f"(x));
    return __uint_as_float(r);
}
__device__ __forceinline__ float softplus_f(float x) {
    return (x > 20.f) ? x : log1pf(expf(x));
}
__device__ __forceinline__ uint32_t smem_u32(const void* p) {
    uint32_t a;
    asm("{ .reg .u64 t; cvta.to.shared.u64 t, %1; cvt.u32.u64 %0, t; }" : "=r"(a) : "l"(p));
    return a;
}
__device__ __forceinline__ void cp16(uint32_t dst, const void* src) {
    asm volatile("cp.async.cg.shared.global [%0], [%1], 16;" :: "r"(dst), "l"(src));
}
#define CP_COMMIT() asm volatile("cp.async.commit_group;" ::: "memory")
#define CP_WAIT0()  asm volatile("cp.async.wait_group 0;" ::: "memory")
#define CP_WAIT1()  asm volatile("cp.async.wait_group 1;" ::: "memory")

// mma.sync m16n8k8 tf32 (sm_80+ baseline feature; valid at compute_103)
__device__ __forceinline__ void mma_16n8k8(
    float& c0, float& c1, float& c2, float& c3,
    uint32_t a0, uint32_t a1, uint32_t a2, uint32_t a3,
    uint32_t b0, uint32_t b1)
{
    asm volatile(
        "mma.sync.aligned.m16n8k8.row.col.f32.tf32.tf32.f32 "
        "{%0,%1,%2,%3}, {%4,%5,%6,%7}, {%8,%9}, {%0,%1,%2,%3};"
        : "+f"(c0), "+f"(c1), "+f"(c2), "+f"(c3)
        : "r"(a0), "r"(a1), "r"(a2), "r"(a3), "r"(b0), "r"(b1));
}

// ---------------------------------------------------------------------------
// tf32 mma.sync GEMM: C[M,N] = A[M,K] @ Bw[N,K]^T
// 128x128 tile, BK=32, 8 warps (4m x 2n), warp tile 32x64, double-buffered.
// MODE: 1 = +bias[n], 2 = +res[m,n]
// ---------------------------------------------------------------------------
#define BM 128
#define BN 128
#define BK 32
#define BKP 36                              // padded row (floats)
#define STG ((BM + BN) * BKP)               // floats per stage
#define MM_SMEM (2 * STG * 4)               // 73728 bytes

__device__ __forceinline__ void mm_load(
    const float* __restrict__ A, const float* __restrict__ Bw, int K,
    int m0, int n0, uint32_t sbyte, int stage, int chunk, int tid)
{
    uint32_t ab = sbyte + (uint32_t)stage * (STG * 4);
    uint32_t bb = ab + BM * BKP * 4;
    const float* Ap = A  + (size_t)m0 * K + chunk * BK;
    const float* Bp = Bw + (size_t)n0 * K + chunk * BK;
    #pragma unroll
    for (int p = 0; p < 4; p++) {
        int idx = tid + (p << 8);
        int r = idx >> 3, c = idx & 7;
        cp16(ab + (uint32_t)(r * BKP + c * 4) * 4, Ap + (size_t)r * K + c * 4);
    }
    #pragma unroll
    for (int p = 0; p < 4; p++) {
        int idx = tid + (p << 8);
        int r = idx >> 3, c = idx & 7;
        cp16(bb + (uint32_t)(r * BKP + c * 4) * 4, Bp + (size_t)r * K + c * 4);
    }
}

template <int MODE>
__global__ void __launch_bounds__(256, 2) mm_gemm(
    const float* __restrict__ A, const float* __restrict__ Bw,
    float* __restrict__ C, const float* __restrict__ bias,
    const float* __restrict__ res, int K, int N)
{
    extern __shared__ float sm[];
    const uint32_t sbyte = smem_u32(sm);
    const int tid  = threadIdx.x;
    const int lane = tid & 31;
    const int wid  = tid >> 5;
    const int wm   = wid >> 1;      // 0..3
    const int wn   = wid & 1;       // 0..1
    const int row  = lane >> 2;     // 0..7
    const int qc   = lane & 3;      // 0..3
    const int m0 = blockIdx.y * BM;
    const int n0 = blockIdx.x * BN;

    float acc[2][8][4];
    #pragma unroll
    for (int i = 0; i < 2; i++)
        #pragma unroll
        for (int j = 0; j < 8; j++)
            #pragma unroll
            for (int q = 0; q < 4; q++) acc[i][j][q] = 0.f;

    const int nc = K / BK;
    mm_load(A, Bw, K, m0, n0, sbyte, 0, 0, tid);
    CP_COMMIT();

    for (int ks = 0; ks < nc; ks++) {
        if (ks + 1 < nc) {
            mm_load(A, Bw, K, m0, n0, sbyte, (ks + 1) & 1, ks + 1, tid);
            CP_COMMIT();
            CP_WAIT1();
        } else {
            CP_WAIT0();
        }
        __syncthreads();

        const float* As = sm + (ks & 1) * STG;
        const float* Bs = As + BM * BKP;
        #pragma unroll
        for (int kk = 0; kk < 4; kk++) {
            int k = kk * 8;
            uint32_t a[2][4];
            #pragma unroll
            for (int mt = 0; mt < 2; mt++) {
                const float* ap = As + (wm * 32 + mt * 16 + row) * BKP + k + qc;
                a[mt][0] = __float_as_uint(ap[0]);
                a[mt][1] = __float_as_uint(ap[8 * BKP]);
                a[mt][2] = __float_as_uint(ap[4]);
                a[mt][3] = __float_as_uint(ap[8 * BKP + 4]);
            }
            uint32_t b[8][2];
            #pragma unroll
            for (int nt = 0; nt < 8; nt++) {
                const float* bp = Bs + (wn * 64 + nt * 8 + row) * BKP + k + qc;
                b[nt][0] = __float_as_uint(bp[0]);
                b[nt][1] = __float_as_uint(bp[4]);
            }
            #pragma unroll
            for (int mt = 0; mt < 2; mt++)
                #pragma unroll
                for (int nt = 0; nt < 8; nt++)
                    mma_16n8k8(acc[mt][nt][0], acc[mt][nt][1],
                               acc[mt][nt][2], acc[mt][nt][3],
                               a[mt][0], a[mt][1], a[mt][2], a[mt][3],
                               b[nt][0], b[nt][1]);
        }
        __syncthreads();
    }

    // epilogue
    #pragma unroll
    for (int mt = 0; mt < 2; mt++) {
        int gr0 = m0 + wm * 32 + mt * 16 + row;
        #pragma unroll
        for (int nt = 0; nt < 8; nt++) {
            int gc = n0 + wn * 64 + nt * 8 + qc * 2;
            float2 v0 = make_float2(acc[mt][nt][0], acc[mt][nt][1]);
            float2 v1 = make_float2(acc[mt][nt][2], acc[mt][nt][3]);
            if (MODE & 1) {
                float2 bb = *(const float2*)(bias + gc);
                v0.x += bb.x; v0.y += bb.y;
                v1.x += bb.x; v1.y += bb.y;
            }
            if (MODE & 2) {
                float2 r0 = *(const float2*)(res + (size_t)gr0 * N + gc);
                float2 r1 = *(const float2*)(res + (size_t)(gr0 + 8) * N + gc);
                v0.x += r0.x; v0.y += r0.y;
                v1.x += r1.x; v1.y += r1.y;
            }
            *(float2*)(C + (size_t)gr0 * N + gc)       = v0;
            *(float2*)(C + (size_t)(gr0 + 8) * N + gc) = v1;
        }
    }
}

// ---------------------------------------------------------------------------
// transpose + tf32 round: in[K,N] -> out[N,K]
// ---------------------------------------------------------------------------
__global__ void __launch_bounds__(256) transpose_tf32(
    const float* __restrict__ in, float* __restrict__ out, int K, int N)
{
    __shared__ float t[32][33];
    int n0 = blockIdx.x * 32, k0 = blockIdx.y * 32;
    int x = threadIdx.x & 31, y = threadIdx.x >> 5;
    #pragma unroll
    for (int i = 0; i < 4; i++)
        t[y + 8 * i][x] = in[(size_t)(k0 + y + 8 * i) * N + n0 + x];
    __syncthreads();
    #pragma unroll
    for (int i = 0; i < 4; i++)
        out[(size_t)(n0 + y + 8 * i) * K + k0 + x] = to_tf32(t[x][y + 8 * i]);
}

// ---------------------------------------------------------------------------
// LayerNorm (tf32-rounded output; feeds tensor GEMMs)
// ---------------------------------------------------------------------------
__global__ void __launch_bounds__(256) ln_kernel(
    const float* __restrict__ x, const float* __restrict__ g,
    const float* __restrict__ b, float* __restrict__ out)
{
    int t = blockIdx.x, tid = threadIdx.x;
    float4 v = ((const float4*)(x + (size_t)t * DMODEL))[tid];
    float s  = v.x + v.y + v.z + v.w;
    float ss = fmaf(v.x, v.x, fmaf(v.y, v.y, fmaf(v.z, v.z, v.w * v.w)));
    #pragma unroll
    for (int o = 16; o > 0; o >>= 1) {
        s  += __shfl_down_sync(0xffffffffu, s, o);
        ss += __shfl_down_sync(0xffffffffu, ss, o);
    }
    __shared__ float rs_[8], rss_[8];
    __shared__ float smu, srs;
    int warp = tid >> 5, lane = tid & 31;
    if (lane == 0) { rs_[warp] = s; rss_[warp] = ss; }
    __syncthreads();
    if (tid == 0) {
        float S = 0.f, SS = 0.f;
        #pragma unroll
        for (int w = 0; w < 8; w++) { S += rs_[w]; SS += rss_[w]; }
        float mu = S * (1.f / DMODEL);
        smu = mu;
        srs = rsqrtf(SS * (1.f / DMODEL) - mu * mu + 1e-5f);
    }
    __syncthreads();
    float mu = smu, rs = srs;
    float4 gv = ((const float4*)g)[tid];
    float4 bv = ((const float4*)b)[tid];
    float4 o;
    o.x = to_tf32((v.x - mu) * rs * gv.x + bv.x);
    o.y = to_tf32((v.y - mu) * rs * gv.y + bv.y);
    o.z = to_tf32((v.z - mu) * rs * gv.z + bv.z);
    o.w = to_tf32((v.w - mu) * rs * gv.w + bv.w);
    ((float4*)(out + (size_t)t * DMODEL))[tid] = o;
}

// ---------------------------------------------------------------------------
// fp32 GEMM (dt projection): C = softplus(A@B + bias), K=64, lda=96
// ---------------------------------------------------------------------------
__global__ void __launch_bounds__(256) gemm_dt(
    const float* __restrict__ A, int lda,
    const float* __restrict__ B, float* __restrict__ C,
    const float* __restrict__ bias, int N, int K)
{
    __shared__ float As[8][128];
    __shared__ float Bs[8][128];
    int tid = threadIdx.x;
    int m0 = blockIdx.y * 128, n0 = blockIdx.x * 128;
    int ar = tid >> 1, ac = (tid & 1) * 4;
    int br = tid >> 5, bc = (tid & 31) * 4;
    int ty = tid >> 4, tx = tid & 15;
    float acc[8][8];
    #pragma unroll
    for (int i = 0; i < 8; i++)
        #pragma unroll
        for (int j = 0; j < 8; j++) acc[i][j] = 0.f;
    for (int k0 = 0; k0 < K; k0 += 8) {
        float4 av = *(const float4*)(A + (size_t)(m0 + ar) * lda + k0 + ac);
        float4 bv = *(const float4*)(B + (size_t)(k0 + br) * N + n0 + bc);
        As[ac + 0][ar] = av.x; As[ac + 1][ar] = av.y;
        As[ac + 2][ar] = av.z; As[ac + 3][ar] = av.w;
        *(float4*)(&Bs[br][bc]) = bv;
        __syncthreads();
        #pragma unroll
        for (int k = 0; k < 8; k++) {
            float a[8], b8[8];
            *(float4*)(a)      = *(const float4*)(&As[k][ty * 8]);
            *(float4*)(a + 4)  = *(const float4*)(&As[k][ty * 8 + 4]);
            *(float4*)(b8)     = *(const float4*)(&Bs[k][tx * 8]);
            *(float4*)(b8 + 4) = *(const float4*)(&Bs[k][tx * 8 + 4]);
            #pragma unroll
            for (int i = 0; i < 8; i++)
                #pragma unroll
                for (int j = 0; j < 8; j++)
                    acc[i][j] = fmaf(a[i], b8[j], acc[i][j]);
        }
        __syncthreads();
    }
    #pragma unroll
    for (int i = 0; i < 8; i++) {
        int rw = m0 + ty * 8 + i;
        #pragma unroll
        for (int j4 = 0; j4 < 8; j4 += 4) {
            int col = n0 + tx * 8 + j4;
            float4 bb = *(const float4*)(bias + col);
            float4 v;
            v.x = softplus_f(acc[i][j4 + 0] + bb.x);
            v.y = softplus_f(acc[i][j4 + 1] + bb.y);
            v.z = softplus_f(acc[i][j4 + 2] + bb.z);
            v.w = softplus_f(acc[i][j4 + 3] + bb.w);
            *(float4*)(C + (size_t)rw * N + col) = v;
        }
    }
}

// ---------------------------------------------------------------------------
__global__ void __launch_bounds__(256) conv_silu_kernel(
    const float* __restrict__ xz, const float* __restrict__ w,
    const float* __restrict__ cb, float* __restrict__ out)
{
    int idx = blockIdx.x * 256 + threadIdx.x;
    int d = idx & (DINNER - 1);
    int t = idx >> 11;
    int l = t & (LSEQ - 1);
    float w0 = w[d * 4 + 0], w1 = w[d * 4 + 1], w2 = w[d * 4 + 2], w3 = w[d * 4 + 3];
    float s = cb[d];
    const float* base = xz + (size_t)t * (2 * DINNER) + d;
    if (l >= 3) s = fmaf(w0, base[-3 * (ptrdiff_t)(2 * DINNER)], s);
    if (l >= 2) s = fmaf(w1, base[-2 * (ptrdiff_t)(2 * DINNER)], s);
    if (l >= 1) s = fmaf(w2, base[-1 * (ptrdiff_t)(2 * DINNER)], s);
    s = fmaf(w3, base[0], s);
    out[idx] = s / (1.f + expf(-s));
}

// ---------------------------------------------------------------------------
// dbc = xc @ w_x  (M=4096, K=2048, N=96) — 16-row tiles -> 256 CTAs
// ---------------------------------------------------------------------------
__global__ void __launch_bounds__(256) wx_kernel(
    const float* __restrict__ A, const float* __restrict__ W,
    float* __restrict__ C)
{
    __shared__ float As[64][17];   // [k][m]
    __shared__ float Ws[64][96];
    int tid = threadIdx.x;
    int m0 = blockIdx.x * 16;
    int tr = tid >> 4;   // row 0..15
    int tc = tid & 15;   // col group: 6 cols
    float acc[6];
    #pragma unroll
    for (int j = 0; j < 6; j++) acc[j] = 0.f;

    for (int k0 = 0; k0 < DINNER; k0 += 64) {
        {
            int r = tid >> 4, c = (tid & 15) * 4;
            float4 v = *(const float4*)(A + (size_t)(m0 + r) * DINNER + k0 + c);
            As[c + 0][r] = v.x; As[c + 1][r] = v.y;
            As[c + 2][r] = v.z; As[c + 3][r] = v.w;
        }
        #pragma unroll
        for (int q = 0; q < 6; q++) {
            int f = tid + 256 * q;
            int r = f / 24, c = (f % 24) * 4;
            *(float4*)(&Ws[r][c]) = *(const float4*)(W + (size_t)(k0 + r) * 96 + c);
        }
        __syncthreads();
        #pragma unroll 8
        for (int k = 0; k < 64; k++) {
            float a = As[k][tr];
            #pragma unroll
            for (int j = 0; j < 6; j++)
                acc[j] = fmaf(a, Ws[k][tc * 6 + j], acc[j]);
        }
        __syncthreads();
    }
    #pragma unroll
    for (int j = 0; j < 6; j++)
        C[(size_t)(m0 + tr) * 96 + tc * 6 + j] = acc[j];
}

// ---------------------------------------------------------------------------
// selective scan (fused skip + silu(z)); tf32-rounded output
// ---------------------------------------------------------------------------
__global__ void __launch_bounds__(256) scan_kernel(
    const float* __restrict__ dt, const float* __restrict__ xc,
    const float* __restrict__ dbc, const float* __restrict__ xz,
    const float* __restrict__ a_log, const float* __restrict__ d_skip,
    float* __restrict__ y)
{
    int warp = threadIdx.x >> 5;
    int lane = threadIdx.x & 31;
    int half = lane >> 4;
    int n    = lane & 15;
    int gchan = blockIdx.x * 16 + warp * 2 + half;
    int b = gchan >> 11;
    int d = gchan & (DINNER - 1);
    float Acoef = -expf(a_log[d * DSTATE + n]);
    float Dsk   = d_skip[d];
    float s = 0.f;
    int t0 = b * LSEQ;
    float dt_c = dt [(size_t)t0 * DINNER + d];
    float x_c  = xc [(size_t)t0 * DINNER + d];
    float B_c  = dbc[(size_t)t0 * 96 + 64 + n];
    float C_c  = dbc[(size_t)t0 * 96 + 80 + n];
    float z_c  = (n == 0) ? xz[(size_t)t0 * (2 * DINNER) + DINNER + d] : 0.f;

    for (int l = 0; l < LSEQ; l++) {
        int t = t0 + l;
        float dt_n = 0.f, x_n = 0.f, B_n = 0.f, C_n = 0.f, z_n = 0.f;
        if (l + 1 < LSEQ) {
            int t2 = t + 1;
            dt_n = dt [(size_t)t2 * DINNER + d];
            x_n  = xc [(size_t)t2 * DINNER + d];
            B_n  = dbc[(size_t)t2 * 96 + 64 + n];
            C_n  = dbc[(size_t)t2 * 96 + 80 + n];
            if (n == 0) z_n = xz[(size_t)t2 * (2 * DINNER) + DINNER + d];
        }
        float dA = __expf(dt_c * Acoef);
        s = fmaf(s, dA, dt_c * x_c * B_c);
        float part = s * C_c;
        part += __shfl_down_sync(0xffffffffu, part, 8, 16);
        part += __shfl_down_sync(0xffffffffu, part, 4, 16);
        part += __shfl_down_sync(0xffffffffu, part, 2, 16);
        part += __shfl_down_sync(0xffffffffu, part, 1, 16);
        if (n == 0) {
            float yv = part + Dsk * x_c;
            yv = yv * (z_c / (1.f + __expf(-z_c)));
            y[(size_t)t * DINNER + d] = to_tf32(yv);
        }
        dt_c = dt_n; x_c = x_n; B_c = B_n; C_c = C_n; z_c = z_n;
    }
}

// ---------------------------------------------------------------------------
// geglu (tf32-rounded output; feeds ff2 GEMM)
// ---------------------------------------------------------------------------
__global__ void __launch_bounds__(256) geglu_kernel(
    const float* __restrict__ p, float* __restrict__ out)
{
    int idx = blockIdx.x * 256 + threadIdx.x;
    int t = idx >> 12;
    int j = idx & (FFIN - 1);
    float a = p[(size_t)t * (2 * FFIN) + j];
    float g = p[(size_t)t * (2 * FFIN) + FFIN + j];
    float inner = 0.7978845608028654f * fmaf(0.044715f * g * g, g, g);
    float ge = 0.5f * g * (1.f + tanhf(inner));
    out[idx] = to_tf32(a * ge);
}

// ---------------------------------------------------------------------------
extern "C" void kernel_launch(void* const* d_in, const int* in_sizes, int n_in,
                              void* d_out, int out_size)
{
    const float* x      = (const float*)d_in[0];
    const float* ln1_g  = (const float*)d_in[1];
    const float* ln1_b  = (const float*)d_in[2];
    const float* w_in   = (const float*)d_in[3];
    const float* conv_w = (const float*)d_in[4];
    const float* conv_b = (const float*)d_in[5];
    const float* w_x    = (const float*)d_in[6];
    const float* w_dt   = (const float*)d_in[7];
    const float* b_dt   = (const float*)d_in[8];
    const float* a_log  = (const float*)d_in[9];
    const float* d_skip = (const float*)d_in[10];
    const float* w_out  = (const float*)d_in[11];
    const float* ln2_g  = (const float*)d_in[12];
    const float* ln2_b  = (const float*)d_in[13];
    const float* w_ff1  = (const float*)d_in[14];
    const float* b_ff1  = (const float*)d_in[15];
    const float* w_ff2  = (const float*)d_in[16];
    const float* b_ff2  = (const float*)d_in[17];
    float* out = (float*)d_out;

    float *h, *xz, *xc, *dbc, *dtb, *y, *out1, *h2, *p, *ffa;
    float *wtin, *wtout, *wtff1, *wtff2;
    cudaGetSymbolAddress((void**)&h,     g_h);
    cudaGetSymbolAddress((void**)&xz,    g_xz);
    cudaGetSymbolAddress((void**)&xc,    g_xc);
    cudaGetSymbolAddress((void**)&dbc,   g_dbc);
    cudaGetSymbolAddress((void**)&dtb,   g_dt);
    cudaGetSymbolAddress((void**)&y,     g_y);
    cudaGetSymbolAddress((void**)&out1,  g_out1);
    cudaGetSymbolAddress((void**)&h2,    g_h2);
    cudaGetSymbolAddress((void**)&p,     g_p);
    cudaGetSymbolAddress((void**)&ffa,   g_ffa);
    cudaGetSymbolAddress((void**)&wtin,  g_wtin);
    cudaGetSymbolAddress((void**)&wtout, g_wtout);
    cudaGetSymbolAddress((void**)&wtff1, g_wtff1);
    cudaGetSymbolAddress((void**)&wtff2, g_wtff2);

    cudaFuncSetAttribute(mm_gemm<0>, cudaFuncAttributeMaxDynamicSharedMemorySize, MM_SMEM);
    cudaFuncSetAttribute(mm_gemm<1>, cudaFuncAttributeMaxDynamicSharedMemorySize, MM_SMEM);
    cudaFuncSetAttribute(mm_gemm<2>, cudaFuncAttributeMaxDynamicSharedMemorySize, MM_SMEM);
    cudaFuncSetAttribute(mm_gemm<3>, cudaFuncAttributeMaxDynamicSharedMemorySize, MM_SMEM);

    // weight transposes ([K,N] -> [N,K], tf32-rounded)
    transpose_tf32<<<dim3(4096 / 32, 1024 / 32), 256>>>(w_in,  wtin,  1024, 4096);
    transpose_tf32<<<dim3(1024 / 32, 2048 / 32), 256>>>(w_out, wtout, 2048, 1024);
    transpose_tf32<<<dim3(8192 / 32, 1024 / 32), 256>>>(w_ff1, wtff1, 1024, 8192);
    transpose_tf32<<<dim3(1024 / 32, 4096 / 32), 256>>>(w_ff2, wtff2, 4096, 1024);

    // 1. ln1
    ln_kernel<<<TOKENS, 256>>>(x, ln1_g, ln1_b, h);
    // 2. xz = h @ w_in
    mm_gemm<0><<<dim3(4096 / BN, TOKENS / BM), 256, MM_SMEM>>>(
        h, wtin, xz, nullptr, nullptr, 1024, 4096);
    // 3. conv + silu
    conv_silu_kernel<<<(TOKENS * DINNER) / 256, 256>>>(xz, conv_w, conv_b, xc);
    // 4. dbc = xc @ w_x
    wx_kernel<<<TOKENS / 16, 256>>>(xc, w_x, dbc);
    // 5. dt = softplus(dt_lo @ w_dt + b_dt)
    gemm_dt<<<dim3(DINNER / 128, TOKENS / 128), 256>>>(
        dbc, 96, w_dt, dtb, b_dt, DINNER, DTRANK);
    // 6. scan
    scan_kernel<<<(2 * DINNER) / 16, 256>>>(dtb, xc, dbc, xz, a_log, d_skip, y);
    // 7. out1 = x + y @ w_out
    mm_gemm<2><<<dim3(DMODEL / BN, TOKENS / BM), 256, MM_SMEM>>>(
        y, wtout, out1, nullptr, x, 2048, DMODEL);
    // 8. ln2
    ln_kernel<<<TOKENS, 256>>>(out1, ln2_g, ln2_b, h2);
    // 9. p = h2 @ w_ff1 + b_ff1
    mm_gemm<1><<<dim3((2 * FFIN) / BN, TOKENS / BM), 256, MM_SMEM>>>(
        h2, wtff1, p, b_ff1, nullptr, 1024, 2 * FFIN);
    // 10. geglu
    geglu_kernel<<<(TOKENS * FFIN) / 256, 256>>>(p, ffa);
    // 11. out = out1 + ffa @ w_ff2 + b_ff2
    mm_gemm<3><<<dim3(DMODEL / BN, TOKENS / BM), 256, MM_SMEM>>>(
        ffa, wtff2, out, b_ff2, out1, FFIN, DMODEL);
}